// round 14
// baseline (speedup 1.0000x reference)
#include <cuda_runtime.h>
#include <cuda_fp16.h>
#include <math.h>
#include <stdint.h>

// Problem sizes (fixed)
#define M_TOTAL 32768
#define K_TOTAL 2048
#define N_TOTAL 2048

// Work-unit tiling
#define BM 128
#define BN 128
#define BK 64
#define NKI    (K_TOTAL / BK)    // 32 k-iters per unit
#define NTILES (N_TOTAL / BN)    // 16 n-tiles per panel
#define PANELS (M_TOTAL / BM)    // 256 panels
#define UNITS  (PANELS * NTILES) // 4096 units
#define THREADS 128              // 4 warps: 2 (M) x 2 (N); warp tile 64x64
#define NWARP 4
#define GRID 296                 // 2 CTAs per SM

#define TILE_HALVES 8192         // one 128x64 fp16 tile = 16 KB
#define TILE_BYTES 16384

// SMEM: 3 stages x (x-tile 16KB + w-tile 16KB) + bias + mbarriers
#define XS_BYTES 16384
#define STAGE_BYTES 32768
#define NSTAGE 3
#define BIAS_OFF (NSTAGE * STAGE_BYTES)          // 98304
#define MBAR_OFF (BIAS_OFF + N_TOTAL * 4)        // 106496
#define SMEM_TOTAL (MBAR_OFF + 64)               // 106560

// fp16 scratch, PRE-SWIZZLED 16KB tiles (exact smem image) + LSE partials
__device__ __half g_x16[(size_t)M_TOTAL * K_TOTAL];    // tiles (panel, kt)
__device__ __half g_wt16[(size_t)N_TOTAL * K_TOTAL];   // tiles (ntile, kt)
__device__ float2 g_part[2 * NTILES][M_TOTAL];         // partial (m, s)

__device__ __forceinline__ uint32_t sw128(uint32_t off) {
    return off ^ ((off >> 3) & 0x70);
}

// ---------------- conversion kernels (emit swizzled tiles) ------------------
// x tile (p, kt): rows = m-local (128), cols = k-local (64). bid = p*32 + kt.
__global__ void conv_x_kernel(const float* __restrict__ src) {
    const int bid = blockIdx.x;
    const int p   = bid >> 5;
    const int kt  = bid & 31;
    const int tid = threadIdx.x;
    __half* tile = g_x16 + (size_t)bid * TILE_HALVES;
    #pragma unroll
    for (int i = 0; i < 4; ++i) {
        int c    = tid + i * 256;       // chunk 0..1023
        int row  = c >> 3;
        int c16  = c & 7;
        const float4* s = reinterpret_cast<const float4*>(
            src + (size_t)(p * 128 + row) * K_TOTAL + kt * 64 + c16 * 8);
        float4 v0 = __ldcs(s);
        float4 v1 = __ldcs(s + 1);
        __half2 h0 = __floats2half2_rn(v0.x, v0.y);
        __half2 h1 = __floats2half2_rn(v0.z, v0.w);
        __half2 h2 = __floats2half2_rn(v1.x, v1.y);
        __half2 h3 = __floats2half2_rn(v1.z, v1.w);
        uint4 o;
        o.x = *reinterpret_cast<unsigned*>(&h0);
        o.y = *reinterpret_cast<unsigned*>(&h1);
        o.z = *reinterpret_cast<unsigned*>(&h2);
        o.w = *reinterpret_cast<unsigned*>(&h3);
        uint32_t sw = sw128(row * 128 + c16 * 16);
        __stcs(reinterpret_cast<uint4*>(reinterpret_cast<char*>(tile) + sw), o);
    }
}

// W tile (nt, kt): rows = n-local (128), cols = k-local (64); W is (K, N) f32.
__global__ void conv_wt_kernel(const float* __restrict__ W) {
    __shared__ float t[64][129];        // t[k-local][n-local]
    const int bid = blockIdx.x;
    const int nt  = bid >> 5;
    const int kt  = bid & 31;
    const int tid = threadIdx.x;
    __half* tile = g_wt16 + (size_t)bid * TILE_HALVES;

    // load 64 k-rows x 128 n-cols f32
    #pragma unroll
    for (int i = 0; i < 8; ++i) {
        int c   = tid + i * 256;        // float4 index 0..2047
        int kr  = c >> 5;               // 0..63
        int nc4 = c & 31;               // 0..31
        float4 v = *reinterpret_cast<const float4*>(
            W + (size_t)(kt * 64 + kr) * N_TOTAL + nt * 128 + nc4 * 4);
        t[kr][nc4 * 4 + 0] = v.x;
        t[kr][nc4 * 4 + 1] = v.y;
        t[kr][nc4 * 4 + 2] = v.z;
        t[kr][nc4 * 4 + 3] = v.w;
    }
    __syncthreads();

    // transpose + convert + swizzle
    #pragma unroll
    for (int i = 0; i < 4; ++i) {
        int c   = tid + i * 256;        // chunk 0..1023
        int nr  = c >> 3;
        int c16 = c & 7;
        __half2 h[4];
        #pragma unroll
        for (int j = 0; j < 4; ++j)
            h[j] = __floats2half2_rn(t[c16 * 8 + j * 2][nr],
                                     t[c16 * 8 + j * 2 + 1][nr]);
        uint4 o;
        o.x = *reinterpret_cast<unsigned*>(&h[0]);
        o.y = *reinterpret_cast<unsigned*>(&h[1]);
        o.z = *reinterpret_cast<unsigned*>(&h[2]);
        o.w = *reinterpret_cast<unsigned*>(&h[3]);
        uint32_t sw = sw128(nr * 128 + c16 * 16);
        *reinterpret_cast<uint4*>(reinterpret_cast<char*>(tile) + sw) = o;
    }
}

// ---------------- mbarrier / bulk-copy helpers ------------------------------
__device__ __forceinline__ uint32_t smem_u32(const void* p) {
    return (uint32_t)__cvta_generic_to_shared(p);
}
__device__ __forceinline__ void mbar_init(uint32_t mbar, uint32_t cnt) {
    asm volatile("mbarrier.init.shared.b64 [%0], %1;" :: "r"(mbar), "r"(cnt) : "memory");
}
__device__ __forceinline__ void mbar_expect_tx(uint32_t mbar, uint32_t bytes) {
    asm volatile("mbarrier.arrive.expect_tx.shared.b64 _, [%0], %1;"
                 :: "r"(mbar), "r"(bytes) : "memory");
}
__device__ __forceinline__ void mbar_arrive(uint32_t mbar) {
    asm volatile("mbarrier.arrive.shared.b64 _, [%0];" :: "r"(mbar) : "memory");
}
__device__ __forceinline__ void mbar_wait(uint32_t mbar, int parity) {
    asm volatile(
        "{\n\t.reg .pred P;\n\t"
        "W_%=:\n\t"
        "mbarrier.try_wait.parity.acquire.cta.shared::cta.b64 P, [%0], %1, 0x989680;\n\t"
        "@P bra.uni D_%=;\n\t"
        "bra.uni W_%=;\n\t"
        "D_%=:\n\t}"
        :: "r"(mbar), "r"(parity) : "memory");
}
__device__ __forceinline__ void bulk_g2s(uint32_t dst, const void* src,
                                         uint32_t bytes, uint32_t mbar) {
    asm volatile(
        "cp.async.bulk.shared::cluster.global.mbarrier::complete_tx::bytes "
        "[%0], [%1], %2, [%3];"
        :: "r"(dst), "l"(src), "r"(bytes), "r"(mbar) : "memory");
}

// ---------------- persistent fused GEMM + per-unit LSE partial --------------
// 4 warps (2M x 2N, warp tile 64x64), mbarrier ring pipeline.
__global__ __launch_bounds__(THREADS, 2)
void gemm_lse_kernel(const float* __restrict__ bias)
{
    extern __shared__ __align__(1024) char smem[];
    const uint32_t sb = smem_u32(smem);
    float* sbias = reinterpret_cast<float*>(smem + BIAS_OFF);

    const int tid  = threadIdx.x;
    const int lane = tid & 31;
    const int wid  = tid >> 5;
    const int wm   = wid >> 1;          // 0..1 : 64-row slab
    const int wn   = wid & 1;           // 0..1 : 64-col slab
    const int qr   = lane >> 2;         // 0..7
    const int qc   = lane & 3;          // 0..3

    // bias -> smem + mbarrier init
    {
        const float4* bsrc = reinterpret_cast<const float4*>(bias);
        float4* bdst = reinterpret_cast<float4*>(sbias);
        #pragma unroll
        for (int i = 0; i < 4; ++i)
            bdst[tid + i * THREADS] = bsrc[tid + i * THREADS];
    }
    if (tid == 0) {
        #pragma unroll
        for (int s = 0; s < NSTAGE; ++s) {
            mbar_init(sb + MBAR_OFF + s * 8, 1);            // full[s]
            mbar_init(sb + MBAR_OFF + 24 + s * 8, NWARP);   // empty[s]
        }
    }
    __syncthreads();

    const int lm_row = lane & 15;
    const int lm_c16 = (lane >> 4) * 16;

    const int b = blockIdx.x;
    const int cnt = (UNITS - b + GRID - 1) / GRID;
    const int G   = cnt * NKI;

    float acc[4][8][4];
    #pragma unroll
    for (int mi = 0; mi < 4; ++mi)
        #pragma unroll
        for (int j = 0; j < 8; ++j)
            #pragma unroll
            for (int c = 0; c < 4; ++c) acc[mi][j][c] = 0.0f;

    int fphase[NSTAGE] = {0, 0, 0};
    int ephase[NSTAGE] = {0, 0, 0};

    // prologue: producer arms stages for g = 0, 1 (both within unit b)
    if (tid == 0) {
        const int p0 = b >> 4, nt0 = b & 15;
        #pragma unroll
        for (int s = 0; s < 2; ++s) {
            uint32_t full = sb + MBAR_OFF + s * 8;
            mbar_expect_tx(full, STAGE_BYTES);
            bulk_g2s(sb + s * STAGE_BYTES,
                     g_x16 + ((size_t)p0 * 32 + s) * TILE_HALVES,
                     TILE_BYTES, full);
            bulk_g2s(sb + s * STAGE_BYTES + XS_BYTES,
                     g_wt16 + ((size_t)nt0 * 32 + s) * TILE_HALVES,
                     TILE_BYTES, full);
        }
    }

    for (int g = 0; g < G; ++g) {
        const int buf = g % NSTAGE;

        // consume: wait for stage data
        mbar_wait(sb + MBAR_OFF + buf * 8, fphase[buf]);
        fphase[buf] ^= 1;

        // producer: arm stage for g+2 (waits until all warps released it)
        if (tid == 0) {
            int g2 = g + 2;
            if (g2 < G) {
                int b2 = g2 % NSTAGE;
                uint32_t full  = sb + MBAR_OFF + b2 * 8;
                uint32_t empty = sb + MBAR_OFF + 24 + b2 * 8;
                if (g2 >= NSTAGE) {
                    mbar_wait(empty, ephase[b2]);
                    ephase[b2] ^= 1;
                }
                int u2 = b + (g2 >> 5) * GRID;
                mbar_expect_tx(full, STAGE_BYTES);
                bulk_g2s(sb + b2 * STAGE_BYTES,
                         g_x16 + (((size_t)(u2 >> 4) << 5) + (g2 & 31)) * TILE_HALVES,
                         TILE_BYTES, full);
                bulk_g2s(sb + b2 * STAGE_BYTES + XS_BYTES,
                         g_wt16 + (((size_t)(u2 & 15) << 5) + (g2 & 31)) * TILE_HALVES,
                         TILE_BYTES, full);
            }
        }

        const uint32_t st = sb + buf * STAGE_BYTES;

        #pragma unroll
        for (int ks = 0; ks < 4; ++ks) {
            unsigned a[4][4];
            #pragma unroll
            for (int mi = 0; mi < 4; ++mi) {
                uint32_t addr = st + sw128(
                    (wm * 64 + mi * 16 + lm_row) * 128 + ks * 32 + lm_c16);
                asm volatile(
                    "ldmatrix.sync.aligned.m8n8.x4.shared.b16 {%0,%1,%2,%3}, [%4];\n"
                    : "=r"(a[mi][0]), "=r"(a[mi][1]), "=r"(a[mi][2]), "=r"(a[mi][3])
                    : "r"(addr));
            }
            unsigned bfr[4][4];
            #pragma unroll
            for (int nb = 0; nb < 4; ++nb) {
                uint32_t addr = st + XS_BYTES + sw128(
                    (wn * 64 + nb * 16 + lm_row) * 128 + ks * 32 + lm_c16);
                asm volatile(
                    "ldmatrix.sync.aligned.m8n8.x4.shared.b16 {%0,%1,%2,%3}, [%4];\n"
                    : "=r"(bfr[nb][0]), "=r"(bfr[nb][1]), "=r"(bfr[nb][2]), "=r"(bfr[nb][3])
                    : "r"(addr));
            }
            #pragma unroll
            for (int mi = 0; mi < 4; ++mi)
                #pragma unroll
                for (int j = 0; j < 8; ++j) {
                    unsigned b0 = bfr[j >> 1][(j & 1)];
                    unsigned b1 = bfr[j >> 1][(j & 1) + 2];
                    asm volatile(
                        "mma.sync.aligned.m16n8k16.row.col.f32.f16.f16.f32 "
                        "{%0,%1,%2,%3}, {%4,%5,%6,%7}, {%8,%9}, {%0,%1,%2,%3};\n"
                        : "+f"(acc[mi][j][0]), "+f"(acc[mi][j][1]),
                          "+f"(acc[mi][j][2]), "+f"(acc[mi][j][3])
                        : "r"(a[mi][0]), "r"(a[mi][1]), "r"(a[mi][2]), "r"(a[mi][3]),
                          "r"(b0), "r"(b1));
                }
        }

        // release stage (per-warp, release semantics order the LDS reads)
        if (lane == 0) mbar_arrive(sb + MBAR_OFF + 24 + buf * 8);

        if ((g & 31) == 31) {
            // ---- unit epilogue: per-warp LSE partial over its 64 cols ----
            const int u  = b + (g >> 5) * GRID;
            const int r0 = (u >> 4) * BM;
            const int nt = u & 15;
            const float* bp = sbias + nt * BN + wn * 64 + qc * 2;

            #pragma unroll
            for (int mi = 0; mi < 4; ++mi)
                #pragma unroll
                for (int h = 0; h < 2; ++h) {
                    float v[16];
                    #pragma unroll
                    for (int j = 0; j < 8; ++j) {
                        v[j * 2]     = acc[mi][j][h * 2]     + bp[j * 8];
                        v[j * 2 + 1] = acc[mi][j][h * 2 + 1] + bp[j * 8 + 1];
                    }
                    float tm = v[0];
                    #pragma unroll
                    for (int c = 1; c < 16; ++c) tm = fmaxf(tm, v[c]);
                    tm = fmaxf(tm, __shfl_xor_sync(0xFFFFFFFFu, tm, 1));
                    tm = fmaxf(tm, __shfl_xor_sync(0xFFFFFFFFu, tm, 2));
                    float s = 0.0f;
                    #pragma unroll
                    for (int c = 0; c < 8; ++c) {
                        __half2 hd = __floats2half2_rn(v[c * 2] - tm,
                                                       v[c * 2 + 1] - tm);
                        float2 e = __half22float2(h2exp(hd));
                        s += e.x + e.y;
                    }
                    s += __shfl_xor_sync(0xFFFFFFFFu, s, 1);
                    s += __shfl_xor_sync(0xFFFFFFFFu, s, 2);
                    if (qc == 0) {
                        int row = wm * 64 + mi * 16 + h * 8 + qr;
                        g_part[nt * 2 + wn][r0 + row] = make_float2(tm, s);
                    }
                    #pragma unroll
                    for (int j = 0; j < 8; ++j) {
                        acc[mi][j][h * 2]     = 0.0f;
                        acc[mi][j][h * 2 + 1] = 0.0f;
                    }
                }
        }
    }

    (void)qr;
}

// ---------------- final combine: 32 partials per row + activation chain ----
__global__ void combine_kernel(float* __restrict__ out) {
    int r = blockIdx.x * 256 + threadIdx.x;

    float2 p[2 * NTILES];
    #pragma unroll
    for (int sl = 0; sl < 2 * NTILES; ++sl)
        p[sl] = __ldcs(&g_part[sl][r]);

    float m = p[0].x;
    #pragma unroll
    for (int sl = 1; sl < 2 * NTILES; ++sl) m = fmaxf(m, p[sl].x);
    float s = 0.0f;
    #pragma unroll
    for (int sl = 0; sl < 2 * NTILES; ++sl)
        s += p[sl].y * __expf(p[sl].x - m);

    float z = m + logf(s);
    z = (z > 0.0f) ? z : 0.01f * z;
    z = (z > 0.0f) ? z : 0.01f * z;
    z = 0.5f * z * (1.0f + erff(z * 0.70710678118654752f));
    z = 0.5f * z * (1.0f + erff(z * 0.70710678118654752f));
    out[r] = z;
}

extern "C" void kernel_launch(void* const* d_in, const int* in_sizes, int n_in,
                              void* d_out, int out_size)
{
    const float* x    = (const float*)d_in[0];   // (M, K) f32 (widened fp16)
    const float* W    = (const float*)d_in[1];   // (K, N) f32
    const float* bias = (const float*)d_in[2];   // (N,)   f32
    float* out        = (float*)d_out;           // (M, 1) f32

    cudaFuncSetAttribute(gemm_lse_kernel,
                         cudaFuncAttributeMaxDynamicSharedMemorySize, SMEM_TOTAL);

    conv_x_kernel<<<PANELS * 32, 256>>>(x);      // 8192 tiles
    conv_wt_kernel<<<NTILES * 32, 256>>>(W);     //  512 tiles
    gemm_lse_kernel<<<GRID, THREADS, SMEM_TOTAL>>>(bias);
    combine_kernel<<<M_TOTAL / 256, 256>>>(out);
}

// round 15
// speedup vs baseline: 1.1468x; 1.1468x over previous
#include <cuda_runtime.h>
#include <cuda_fp16.h>
#include <math.h>
#include <stdint.h>

// Problem sizes (fixed)
#define M_TOTAL 32768
#define K_TOTAL 2048
#define N_TOTAL 2048

// Work-unit tiling
#define BM 128
#define BN 128
#define BK 64
#define NKI    (K_TOTAL / BK)    // 32 k-iters per unit
#define NTILES (N_TOTAL / BN)    // 16 n-tiles per panel
#define PANELS (M_TOTAL / BM)    // 256 panels
#define UNITS  (PANELS * NTILES) // 4096 units
#define THREADS 256              // 8 warps: 4 (M) x 2 (N); warp tile 32x64
#define NWARP 8
#define GRID 296                 // 2 CTAs per SM

#define TILE_HALVES 8192         // one 128x64 fp16 tile = 16 KB
#define TILE_BYTES 16384

// SMEM: 3 stages x (x-tile 16KB + w-tile 16KB) + bias + mbarriers
#define XS_BYTES 16384
#define STAGE_BYTES 32768
#define NSTAGE 3
#define BIAS_OFF (NSTAGE * STAGE_BYTES)          // 98304
#define MBAR_OFF (BIAS_OFF + N_TOTAL * 4)        // 106496
#define SMEM_TOTAL (MBAR_OFF + 64)               // 106560

// fp16 scratch, PRE-SWIZZLED 16KB tiles (exact smem image) + LSE partials
__device__ __half g_x16[(size_t)M_TOTAL * K_TOTAL];    // tiles (panel, kt)
__device__ __half g_wt16[(size_t)N_TOTAL * K_TOTAL];   // tiles (ntile, kt)
__device__ float2 g_part[2 * NTILES][M_TOTAL];         // partial (m, s)

__device__ __forceinline__ uint32_t sw128(uint32_t off) {
    return off ^ ((off >> 3) & 0x70);
}

// ---------------- conversion kernels (emit swizzled tiles) ------------------
// x tile (p, kt): rows = m-local (128), cols = k-local (64). bid = p*32 + kt.
__global__ void conv_x_kernel(const float* __restrict__ src) {
    const int bid = blockIdx.x;
    const int p   = bid >> 5;
    const int kt  = bid & 31;
    const int tid = threadIdx.x;
    __half* tile = g_x16 + (size_t)bid * TILE_HALVES;
    #pragma unroll
    for (int i = 0; i < 4; ++i) {
        int c    = tid + i * 256;       // chunk 0..1023
        int row  = c >> 3;
        int c16  = c & 7;
        const float4* s = reinterpret_cast<const float4*>(
            src + (size_t)(p * 128 + row) * K_TOTAL + kt * 64 + c16 * 8);
        float4 v0 = __ldcs(s);
        float4 v1 = __ldcs(s + 1);
        __half2 h0 = __floats2half2_rn(v0.x, v0.y);
        __half2 h1 = __floats2half2_rn(v0.z, v0.w);
        __half2 h2 = __floats2half2_rn(v1.x, v1.y);
        __half2 h3 = __floats2half2_rn(v1.z, v1.w);
        uint4 o;
        o.x = *reinterpret_cast<unsigned*>(&h0);
        o.y = *reinterpret_cast<unsigned*>(&h1);
        o.z = *reinterpret_cast<unsigned*>(&h2);
        o.w = *reinterpret_cast<unsigned*>(&h3);
        uint32_t sw = sw128(row * 128 + c16 * 16);
        __stcs(reinterpret_cast<uint4*>(reinterpret_cast<char*>(tile) + sw), o);
    }
}

// W tile (nt, kt): rows = n-local (128), cols = k-local (64); W is (K, N) f32.
__global__ void conv_wt_kernel(const float* __restrict__ W) {
    __shared__ float t[64][129];        // t[k-local][n-local]
    const int bid = blockIdx.x;
    const int nt  = bid >> 5;
    const int kt  = bid & 31;
    const int tid = threadIdx.x;
    __half* tile = g_wt16 + (size_t)bid * TILE_HALVES;

    // load 64 k-rows x 128 n-cols f32
    #pragma unroll
    for (int i = 0; i < 8; ++i) {
        int c   = tid + i * 256;        // float4 index 0..2047
        int kr  = c >> 5;               // 0..63
        int nc4 = c & 31;               // 0..31
        float4 v = *reinterpret_cast<const float4*>(
            W + (size_t)(kt * 64 + kr) * N_TOTAL + nt * 128 + nc4 * 4);
        t[kr][nc4 * 4 + 0] = v.x;
        t[kr][nc4 * 4 + 1] = v.y;
        t[kr][nc4 * 4 + 2] = v.z;
        t[kr][nc4 * 4 + 3] = v.w;
    }
    __syncthreads();

    // transpose + convert + swizzle
    #pragma unroll
    for (int i = 0; i < 4; ++i) {
        int c   = tid + i * 256;        // chunk 0..1023
        int nr  = c >> 3;
        int c16 = c & 7;
        __half2 h[4];
        #pragma unroll
        for (int j = 0; j < 4; ++j)
            h[j] = __floats2half2_rn(t[c16 * 8 + j * 2][nr],
                                     t[c16 * 8 + j * 2 + 1][nr]);
        uint4 o;
        o.x = *reinterpret_cast<unsigned*>(&h[0]);
        o.y = *reinterpret_cast<unsigned*>(&h[1]);
        o.z = *reinterpret_cast<unsigned*>(&h[2]);
        o.w = *reinterpret_cast<unsigned*>(&h[3]);
        uint32_t sw = sw128(nr * 128 + c16 * 16);
        *reinterpret_cast<uint4*>(reinterpret_cast<char*>(tile) + sw) = o;
    }
}

// ---------------- mbarrier / bulk-copy helpers ------------------------------
__device__ __forceinline__ uint32_t smem_u32(const void* p) {
    return (uint32_t)__cvta_generic_to_shared(p);
}
__device__ __forceinline__ void mbar_init(uint32_t mbar, uint32_t cnt) {
    asm volatile("mbarrier.init.shared.b64 [%0], %1;" :: "r"(mbar), "r"(cnt) : "memory");
}
__device__ __forceinline__ void mbar_expect_tx(uint32_t mbar, uint32_t bytes) {
    asm volatile("mbarrier.arrive.expect_tx.shared.b64 _, [%0], %1;"
                 :: "r"(mbar), "r"(bytes) : "memory");
}
__device__ __forceinline__ void mbar_arrive(uint32_t mbar) {
    asm volatile("mbarrier.arrive.shared.b64 _, [%0];" :: "r"(mbar) : "memory");
}
__device__ __forceinline__ void mbar_wait(uint32_t mbar, int parity) {
    asm volatile(
        "{\n\t.reg .pred P;\n\t"
        "W_%=:\n\t"
        "mbarrier.try_wait.parity.acquire.cta.shared::cta.b64 P, [%0], %1, 0x989680;\n\t"
        "@P bra.uni D_%=;\n\t"
        "bra.uni W_%=;\n\t"
        "D_%=:\n\t}"
        :: "r"(mbar), "r"(parity) : "memory");
}
__device__ __forceinline__ void bulk_g2s(uint32_t dst, const void* src,
                                         uint32_t bytes, uint32_t mbar) {
    asm volatile(
        "cp.async.bulk.shared::cluster.global.mbarrier::complete_tx::bytes "
        "[%0], [%1], %2, [%3];"
        :: "r"(dst), "l"(src), "r"(bytes), "r"(mbar) : "memory");
}

// ---------------- persistent fused GEMM + per-unit LSE partial --------------
// 8 warps (4M x 2N, warp tile 32x64). mbarrier ring; stage s is produced by
// warp s's lane 0 (rotating producer spreads the arming cost over 3 warps).
__global__ __launch_bounds__(THREADS, 2)
void gemm_lse_kernel(const float* __restrict__ bias)
{
    extern __shared__ __align__(1024) char smem[];
    const uint32_t sb = smem_u32(smem);
    float* sbias = reinterpret_cast<float*>(smem + BIAS_OFF);

    const int tid  = threadIdx.x;
    const int lane = tid & 31;
    const int wid  = tid >> 5;
    const int wm   = wid >> 1;          // 0..3 : 32-row slab
    const int wn   = wid & 1;           // 0..1 : 64-col slab
    const int qr   = lane >> 2;         // 0..7
    const int qc   = lane & 3;          // 0..3

    // bias -> smem + mbarrier init
    {
        const float4* bsrc = reinterpret_cast<const float4*>(bias);
        float4* bdst = reinterpret_cast<float4*>(sbias);
        bdst[tid]       = bsrc[tid];
        bdst[tid + 256] = bsrc[tid + 256];
    }
    if (tid == 0) {
        #pragma unroll
        for (int s = 0; s < NSTAGE; ++s) {
            mbar_init(sb + MBAR_OFF + s * 8, 1);            // full[s]
            mbar_init(sb + MBAR_OFF + 24 + s * 8, NWARP);   // empty[s]
        }
    }
    __syncthreads();

    const int lm_row = lane & 15;
    const int lm_c16 = (lane >> 4) * 16;

    const int b = blockIdx.x;
    const int cnt = (UNITS - b + GRID - 1) / GRID;
    const int G   = cnt * NKI;

    float acc[2][8][4];
    #pragma unroll
    for (int mi = 0; mi < 2; ++mi)
        #pragma unroll
        for (int j = 0; j < 8; ++j)
            #pragma unroll
            for (int c = 0; c < 4; ++c) acc[mi][j][c] = 0.0f;

    int fphase[NSTAGE] = {0, 0, 0};
    int ephase = 0;   // only the owning warp's stage matters

    // prologue: warps 0 and 1 (lane 0) arm stages 0 and 1 (both in unit b)
    if (lane == 0 && wid < 2) {
        const int s = wid;
        const int p0 = b >> 4, nt0 = b & 15;
        uint32_t full = sb + MBAR_OFF + s * 8;
        mbar_expect_tx(full, STAGE_BYTES);
        bulk_g2s(sb + s * STAGE_BYTES,
                 g_x16 + ((size_t)p0 * 32 + s) * TILE_HALVES,
                 TILE_BYTES, full);
        bulk_g2s(sb + s * STAGE_BYTES + XS_BYTES,
                 g_wt16 + ((size_t)nt0 * 32 + s) * TILE_HALVES,
                 TILE_BYTES, full);
    }

    for (int g = 0; g < G; ++g) {
        const int buf = g % NSTAGE;

        // consume: wait for stage data
        mbar_wait(sb + MBAR_OFF + buf * 8, fphase[buf]);
        fphase[buf] ^= 1;

        // rotating producer: warp (g2 % NSTAGE) lane 0 arms stage for g+2
        {
            int g2 = g + 2;
            if (g2 < G && lane == 0 && wid == (g2 % NSTAGE)) {
                const int b2 = wid;   // == g2 % NSTAGE
                uint32_t full  = sb + MBAR_OFF + b2 * 8;
                uint32_t empty = sb + MBAR_OFF + 24 + b2 * 8;
                if (g2 >= NSTAGE) {
                    mbar_wait(empty, ephase);
                    ephase ^= 1;
                }
                int u2 = b + (g2 >> 5) * GRID;
                mbar_expect_tx(full, STAGE_BYTES);
                bulk_g2s(sb + b2 * STAGE_BYTES,
                         g_x16 + (((size_t)(u2 >> 4) << 5) + (g2 & 31)) * TILE_HALVES,
                         TILE_BYTES, full);
                bulk_g2s(sb + b2 * STAGE_BYTES + XS_BYTES,
                         g_wt16 + (((size_t)(u2 & 15) << 5) + (g2 & 31)) * TILE_HALVES,
                         TILE_BYTES, full);
            }
        }

        const uint32_t st = sb + buf * STAGE_BYTES;

        #pragma unroll
        for (int ks = 0; ks < 4; ++ks) {
            unsigned a[2][4];
            #pragma unroll
            for (int mi = 0; mi < 2; ++mi) {
                uint32_t addr = st + sw128(
                    (wm * 32 + mi * 16 + lm_row) * 128 + ks * 32 + lm_c16);
                asm volatile(
                    "ldmatrix.sync.aligned.m8n8.x4.shared.b16 {%0,%1,%2,%3}, [%4];\n"
                    : "=r"(a[mi][0]), "=r"(a[mi][1]), "=r"(a[mi][2]), "=r"(a[mi][3])
                    : "r"(addr));
            }
            unsigned bfr[4][4];
            #pragma unroll
            for (int nb = 0; nb < 4; ++nb) {
                uint32_t addr = st + XS_BYTES + sw128(
                    (wn * 64 + nb * 16 + lm_row) * 128 + ks * 32 + lm_c16);
                asm volatile(
                    "ldmatrix.sync.aligned.m8n8.x4.shared.b16 {%0,%1,%2,%3}, [%4];\n"
                    : "=r"(bfr[nb][0]), "=r"(bfr[nb][1]), "=r"(bfr[nb][2]), "=r"(bfr[nb][3])
                    : "r"(addr));
            }
            #pragma unroll
            for (int mi = 0; mi < 2; ++mi)
                #pragma unroll
                for (int j = 0; j < 8; ++j) {
                    unsigned b0 = bfr[j >> 1][(j & 1)];
                    unsigned b1 = bfr[j >> 1][(j & 1) + 2];
                    asm volatile(
                        "mma.sync.aligned.m16n8k16.row.col.f32.f16.f16.f32 "
                        "{%0,%1,%2,%3}, {%4,%5,%6,%7}, {%8,%9}, {%0,%1,%2,%3};\n"
                        : "+f"(acc[mi][j][0]), "+f"(acc[mi][j][1]),
                          "+f"(acc[mi][j][2]), "+f"(acc[mi][j][3])
                        : "r"(a[mi][0]), "r"(a[mi][1]), "r"(a[mi][2]), "r"(a[mi][3]),
                          "r"(b0), "r"(b1));
                }
        }

        // release stage (per-warp, release semantics order the LDS reads)
        if (lane == 0) mbar_arrive(sb + MBAR_OFF + 24 + buf * 8);

        if ((g & 31) == 31) {
            // ---- unit epilogue: per-warp LSE partial over its 64 cols ----
            const int u  = b + (g >> 5) * GRID;
            const int r0 = (u >> 4) * BM;
            const int nt = u & 15;
            const float* bp = sbias + nt * BN + wn * 64 + qc * 2;

            #pragma unroll
            for (int mi = 0; mi < 2; ++mi)
                #pragma unroll
                for (int h = 0; h < 2; ++h) {
                    float v[16];
                    #pragma unroll
                    for (int j = 0; j < 8; ++j) {
                        v[j * 2]     = acc[mi][j][h * 2]     + bp[j * 8];
                        v[j * 2 + 1] = acc[mi][j][h * 2 + 1] + bp[j * 8 + 1];
                    }
                    float tm = v[0];
                    #pragma unroll
                    for (int c = 1; c < 16; ++c) tm = fmaxf(tm, v[c]);
                    tm = fmaxf(tm, __shfl_xor_sync(0xFFFFFFFFu, tm, 1));
                    tm = fmaxf(tm, __shfl_xor_sync(0xFFFFFFFFu, tm, 2));
                    float s = 0.0f;
                    #pragma unroll
                    for (int c = 0; c < 8; ++c) {
                        __half2 hd = __floats2half2_rn(v[c * 2] - tm,
                                                       v[c * 2 + 1] - tm);
                        float2 e = __half22float2(h2exp(hd));
                        s += e.x + e.y;
                    }
                    s += __shfl_xor_sync(0xFFFFFFFFu, s, 1);
                    s += __shfl_xor_sync(0xFFFFFFFFu, s, 2);
                    if (qc == 0) {
                        int row = wm * 32 + mi * 16 + h * 8 + qr;
                        g_part[nt * 2 + wn][r0 + row] = make_float2(tm, s);
                    }
                    #pragma unroll
                    for (int j = 0; j < 8; ++j) {
                        acc[mi][j][h * 2]     = 0.0f;
                        acc[mi][j][h * 2 + 1] = 0.0f;
                    }
                }
        }
    }

    (void)qr;
}

// ---------------- final combine: 32 partials per row + activation chain ----
__global__ void combine_kernel(float* __restrict__ out) {
    int r = blockIdx.x * 256 + threadIdx.x;

    float2 p[2 * NTILES];
    #pragma unroll
    for (int sl = 0; sl < 2 * NTILES; ++sl)
        p[sl] = __ldcs(&g_part[sl][r]);

    float m = p[0].x;
    #pragma unroll
    for (int sl = 1; sl < 2 * NTILES; ++sl) m = fmaxf(m, p[sl].x);
    float s = 0.0f;
    #pragma unroll
    for (int sl = 0; sl < 2 * NTILES; ++sl)
        s += p[sl].y * __expf(p[sl].x - m);

    float z = m + logf(s);
    z = (z > 0.0f) ? z : 0.01f * z;
    z = (z > 0.0f) ? z : 0.01f * z;
    z = 0.5f * z * (1.0f + erff(z * 0.70710678118654752f));
    z = 0.5f * z * (1.0f + erff(z * 0.70710678118654752f));
    out[r] = z;
}

extern "C" void kernel_launch(void* const* d_in, const int* in_sizes, int n_in,
                              void* d_out, int out_size)
{
    const float* x    = (const float*)d_in[0];   // (M, K) f32 (widened fp16)
    const float* W    = (const float*)d_in[1];   // (K, N) f32
    const float* bias = (const float*)d_in[2];   // (N,)   f32
    float* out        = (float*)d_out;           // (M, 1) f32

    cudaFuncSetAttribute(gemm_lse_kernel,
                         cudaFuncAttributeMaxDynamicSharedMemorySize, SMEM_TOTAL);

    conv_x_kernel<<<PANELS * 32, 256>>>(x);      // 8192 tiles
    conv_wt_kernel<<<NTILES * 32, 256>>>(W);     //  512 tiles
    gemm_lse_kernel<<<GRID, THREADS, SMEM_TOTAL>>>(bias);
    combine_kernel<<<M_TOTAL / 256, 256>>>(out);
}